// round 2
// baseline (speedup 1.0000x reference)
#include <cuda_runtime.h>
#include <cstdint>

// ResidualNet: hash-grid encode (4 levels, T=2^19, F=2) + MLP 8->64->64->1
// Inputs (metadata order):
//   d_in[0] xyz    [N,3] f32   (N = 2,000,000)
//   d_in[1] tables [4, 524288, 2] f32
//   d_in[2] W_in   [8,64] f32
//   d_in[3] W_h    [64,64] f32
//   d_in[4] W_out  [64,1] f32
// Output: sdf [N] f32

#define TSIZE (1u << 19)
#define TMASK (TSIZE - 1u)

__device__ __forceinline__ float leaky(float v) {
    return v >= 0.0f ? v : 0.01f * v;
}

extern "C" __global__ void __launch_bounds__(128, 4)
resnet_fused_kernel(const float* __restrict__ xyz,
                    const float* __restrict__ tables,
                    const float* __restrict__ W_in,
                    const float* __restrict__ W_h,
                    const float* __restrict__ W_out,
                    float* __restrict__ out,
                    int N)
{
    __shared__ float sWin[8 * 64];
    __shared__ float sWh[64 * 64];
    __shared__ float sWo[64];

    for (int i = threadIdx.x; i < 8 * 64; i += 128)  sWin[i] = W_in[i];
    for (int i = threadIdx.x; i < 64 * 64; i += 128) sWh[i]  = W_h[i];
    if (threadIdx.x < 64) sWo[threadIdx.x] = W_out[threadIdx.x];
    __syncthreads();

    int i = blockIdx.x * 128 + threadIdx.x;
    if (i >= N) return;

    // scale_with_bound: map into [0,1]^3  (match reference: (x - lo) / dis)
    float px = (xyz[3 * i + 0] + 5.0f) / 10.0f;
    float py = (xyz[3 * i + 1] + 5.0f) / 10.0f;
    float pz = (xyz[3 * i + 2] + 5.0f) / 10.0f;

    // ---- hash grid encode: 4 levels x 2 features ----
    float enc[8];
    #pragma unroll
    for (int l = 0; l < 4; l++) {
        float res = (float)(200 << l);   // 200, 400, 800, 1600 (exact in f32)
        float fx = px * res, fy = py * res, fz = pz * res;
        float bx = floorf(fx), by = floorf(fy), bz = floorf(fz);
        float tx = fx - bx, ty = fy - by, tz = fz - bz;
        unsigned ux = (unsigned)bx, uy = (unsigned)by, uz = (unsigned)bz;

        const float2* tab = (const float2*)(tables + (size_t)l * TSIZE * 2u);

        float wx[2] = {1.0f - tx, tx};
        float wy[2] = {1.0f - ty, ty};
        float wz[2] = {1.0f - tz, tz};

        float f0 = 0.0f, f1 = 0.0f;
        #pragma unroll
        for (int c = 0; c < 8; c++) {
            unsigned cx = ux + (unsigned)(c & 1);
            unsigned cy = uy + (unsigned)((c >> 1) & 1);
            unsigned cz = uz + (unsigned)((c >> 2) & 1);
            unsigned h = cx ^ (cy * 2654435761u) ^ (cz * 805459861u);
            float2 f = __ldg(&tab[h & TMASK]);
            float w = wx[c & 1] * wy[(c >> 1) & 1] * wz[(c >> 2) & 1];
            f0 = fmaf(f.x, w, f0);
            f1 = fmaf(f.y, w, f1);
        }
        enc[2 * l + 0] = f0;
        enc[2 * l + 1] = f1;
    }

    // ---- layer 1: enc[8] @ W_in[8,64], leaky ----
    float h1[64];
    #pragma unroll
    for (int j = 0; j < 64; j += 4) {
        float4 a = make_float4(0.f, 0.f, 0.f, 0.f);
        #pragma unroll
        for (int k = 0; k < 8; k++) {
            float4 w = *(const float4*)&sWin[k * 64 + j];
            float e = enc[k];
            a.x = fmaf(e, w.x, a.x);
            a.y = fmaf(e, w.y, a.y);
            a.z = fmaf(e, w.z, a.z);
            a.w = fmaf(e, w.w, a.w);
        }
        h1[j + 0] = leaky(a.x);
        h1[j + 1] = leaky(a.y);
        h1[j + 2] = leaky(a.z);
        h1[j + 3] = leaky(a.w);
    }

    // ---- layer 2 (h1 @ W_h, leaky) fused with layer 3 (dot with W_out) ----
    float result = 0.0f;
    #pragma unroll
    for (int j0 = 0; j0 < 64; j0 += 16) {
        float4 a0 = make_float4(0.f, 0.f, 0.f, 0.f);
        float4 a1 = make_float4(0.f, 0.f, 0.f, 0.f);
        float4 a2 = make_float4(0.f, 0.f, 0.f, 0.f);
        float4 a3 = make_float4(0.f, 0.f, 0.f, 0.f);
        #pragma unroll
        for (int k = 0; k < 64; k++) {
            float hk = h1[k];
            const float4* w = (const float4*)&sWh[k * 64 + j0];
            float4 w0 = w[0], w1 = w[1], w2 = w[2], w3 = w[3];
            a0.x = fmaf(hk, w0.x, a0.x); a0.y = fmaf(hk, w0.y, a0.y);
            a0.z = fmaf(hk, w0.z, a0.z); a0.w = fmaf(hk, w0.w, a0.w);
            a1.x = fmaf(hk, w1.x, a1.x); a1.y = fmaf(hk, w1.y, a1.y);
            a1.z = fmaf(hk, w1.z, a1.z); a1.w = fmaf(hk, w1.w, a1.w);
            a2.x = fmaf(hk, w2.x, a2.x); a2.y = fmaf(hk, w2.y, a2.y);
            a2.z = fmaf(hk, w2.z, a2.z); a2.w = fmaf(hk, w2.w, a2.w);
            a3.x = fmaf(hk, w3.x, a3.x); a3.y = fmaf(hk, w3.y, a3.y);
            a3.z = fmaf(hk, w3.z, a3.z); a3.w = fmaf(hk, w3.w, a3.w);
        }
        const float4* wo = (const float4*)&sWo[j0];
        float4 o0 = wo[0], o1 = wo[1], o2 = wo[2], o3 = wo[3];
        result += leaky(a0.x) * o0.x + leaky(a0.y) * o0.y
                + leaky(a0.z) * o0.z + leaky(a0.w) * o0.w;
        result += leaky(a1.x) * o1.x + leaky(a1.y) * o1.y
                + leaky(a1.z) * o1.z + leaky(a1.w) * o1.w;
        result += leaky(a2.x) * o2.x + leaky(a2.y) * o2.y
                + leaky(a2.z) * o2.z + leaky(a2.w) * o2.w;
        result += leaky(a3.x) * o3.x + leaky(a3.y) * o3.y
                + leaky(a3.z) * o3.z + leaky(a3.w) * o3.w;
    }

    out[i] = result * 0.1f;
}

extern "C" void kernel_launch(void* const* d_in, const int* in_sizes, int n_in,
                              void* d_out, int out_size) {
    const float* xyz    = (const float*)d_in[0];
    const float* tables = (const float*)d_in[1];
    const float* W_in   = (const float*)d_in[2];
    const float* W_h    = (const float*)d_in[3];
    const float* W_out  = (const float*)d_in[4];
    float* out = (float*)d_out;

    int N = in_sizes[0] / 3;
    int blocks = (N + 127) / 128;
    resnet_fused_kernel<<<blocks, 128>>>(xyz, tables, W_in, W_h, W_out, out, N);
}